// round 15
// baseline (speedup 1.0000x reference)
#include <cuda_runtime.h>
#include <cuda_fp16.h>

typedef unsigned long long ull;

constexpr int cN = 256, cC = 64, cT = 128, cV = 25, cO = 64;
constexpr int TV  = cT * cV;          // 3200 contiguous (t,v) per (n, channel)

// scratch (no allocations allowed)
__device__ float   g_xsum[cN * cC * cV];                    // 1.6 MB
__device__ float   g_att[(size_t)cN * cO * cV * cV];        // 41 MB
__device__ __half2 g_vtenh[(size_t)cN * cO * TV / 2];       // 105 MB

__device__ __forceinline__ float2 u2f(ull v) {
    float2 r;
    asm("mov.b64 {%0, %1}, %2;" : "=f"(r.x), "=f"(r.y) : "l"(v));
    return r;
}

// ---------------------------------------------------------------------------
// K1: xsum[n,c,v] = sum_t x[n,c,t,v]   (HBM-roof bound, ~40us, keep)
// ---------------------------------------------------------------------------
__global__ void k_sum_t(const float* __restrict__ x) {
    int n = blockIdx.y;
    int c = blockIdx.x * 8 + (threadIdx.x >> 5);
    int lane = threadIdx.x & 31;
    if (lane < cV) {
        const float* p = x + ((size_t)(n * cC + c) * cT) * cV + lane;
        float s = 0.f;
        #pragma unroll 8
        for (int t = 0; t < cT; ++t) s += p[t * cV];
        g_xsum[(n * cC + c) * cV + lane] = s;
    }
}

// ---------------------------------------------------------------------------
// K2: attention matrix (keep)
// ---------------------------------------------------------------------------
__global__ void __launch_bounds__(256) k_att_kernel(
    const float* __restrict__ adj,
    const float* __restrict__ Wk, const float* __restrict__ bk,
    const float* __restrict__ Wq, const float* __restrict__ bq,
    const float* __restrict__ c1w, const float* __restrict__ c1b,
    const float* __restrict__ c2w, const float* __restrict__ c2b,
    const float* __restrict__ fw,  const float* __restrict__ fb,
    const float* __restrict__ alpha) {
    __shared__ float xs2[cC * cV];
    __shared__ float ksh[4 * cV], qsh[4 * cV];
    __shared__ float fwal[cO * 8];              // alpha * fw
    __shared__ float adjsh[cV * cV];
    __shared__ float aa[625 * 9];               // tanh features, stride 9
    __shared__ float c1sh[16], c2sh[16], c1bs[4], c2bs[4], fbal[cO], bks[4], bqs[4];

    int n = blockIdx.y, oh = blockIdx.x, tid = threadIdx.x;
    float al = alpha[0];
    for (int i = tid; i < cC * cV; i += 256) xs2[i] = g_xsum[n * cC * cV + i];
    for (int i = tid; i < cO * 8; i += 256)  fwal[i] = al * fw[i];
    for (int i = tid; i < cV * cV; i += 256) adjsh[i] = adj[i];
    if (tid < 16) { c1sh[tid] = c1w[tid]; c2sh[tid] = c2w[tid]; }
    if (tid < 4)  { c1bs[tid] = c1b[tid]; c2bs[tid] = c2b[tid]; bks[tid] = bk[tid]; bqs[tid] = bq[tid]; }
    if (tid < cO) fbal[tid] = al * fb[tid];
    __syncthreads();

    if (tid < 100) {
        int r = tid / cV, v = tid % cV;
        float a = 0.f;
        for (int c = 0; c < cC; ++c) a += Wk[r * cC + c] * xs2[c * cV + v];
        ksh[tid] = a * (1.f / cT) + bks[r];
    } else if (tid < 200) {
        int j = tid - 100;
        int r = j / cV, v = j % cV;
        float a = 0.f;
        for (int c = 0; c < cC; ++c) a += Wq[r * cC + c] * xs2[c * cV + v];
        qsh[j] = a * (1.f / cT) + bqs[r];
    }
    __syncthreads();

    for (int p = tid; p < 625; p += 256) {
        int v = p / cV, u = p - v * cV;
        float kv[4], qu[4];
        #pragma unroll
        for (int r = 0; r < 4; ++r) { kv[r] = ksh[r * cV + v]; qu[r] = qsh[r * cV + u]; }
        #pragma unroll
        for (int s = 0; s < 4; ++s) {
            float s1 = c1bs[s], s2 = c2bs[s];
            #pragma unroll
            for (int r = 0; r < 4; ++r) {
                s1 += c1sh[s * 4 + r] * (kv[r] * qu[r]);
                s2 += c2sh[s * 4 + r] * (kv[r] - qu[r]);
            }
            aa[p * 9 + s]     = tanhf(s1);
            aa[p * 9 + 4 + s] = tanhf(s2);
        }
    }
    __syncthreads();

    int o0 = oh * 32;
    for (int o = o0; o < o0 + 32; ++o) {
        float w0 = fwal[o*8+0], w1 = fwal[o*8+1], w2 = fwal[o*8+2], w3 = fwal[o*8+3];
        float w4 = fwal[o*8+4], w5 = fwal[o*8+5], w6 = fwal[o*8+6], w7 = fwal[o*8+7];
        float fb_ = fbal[o];
        float* dst = g_att + (size_t)(n * cO + o) * 625;
        for (int p = tid; p < 625; p += 256) {
            const float* a = aa + p * 9;
            float acc = fb_ + adjsh[p];
            acc += w0 * a[0]; acc += w1 * a[1]; acc += w2 * a[2]; acc += w3 * a[3];
            acc += w4 * a[4]; acc += w5 * a[5]; acc += w6 * a[6]; acc += w7 * a[7];
            dst[p] = acc;
        }
    }
}

// ---------------------------------------------------------------------------
// K3 v3: vten[n,o,i] = sum_c Wv[o,c]*x[n,c,i] + bv[o]  -> fp16 store
// 256 thr, warp-uniform o-slice: warp w owns o in [8w, 8w+8); lane owns 4 i.
// wT[c][o] = (w,w) dup -> the 8 per-c weights are consecutive ull: loaded as
// 4 TRUE-BROADCAST LDS.128 (1 wf each). x: 1 conflict-free LDS.128 (4 wf).
// Per c per warp: 8 wf vs 16 FFMA2 -> crossbar/FMA balanced at the FMA floor.
// acc = 16 ull = 32 regs. smem 64KB -> 3 blocks/SM, 24 warps.
// ---------------------------------------------------------------------------
constexpr int CH = 128;  // i-chunk

__global__ void __launch_bounds__(256, 3) k_vten(
    const float* __restrict__ x, const float* __restrict__ Wv,
    const float* __restrict__ bv) {
    __shared__ __align__(16) float xs[cC * CH];   // 32 KB
    __shared__ __align__(16) ull   wT[cC * cO];   // 32 KB: wT[c*64+o] = dup Wv[o][c]

    int n   = blockIdx.y;
    int i0c = blockIdx.x * CH;
    int tid = threadIdx.x;

    // stage x chunk: 2048 float4, coalesced
    for (int i = tid; i < cC * (CH / 4); i += 256) {
        int c = i >> 5, j = i & 31;
        ((float4*)xs)[i] =
            ((const float4*)(x + (size_t)(n * cC + c) * TV + i0c))[j];
    }
    // stage transposed+duplicated weights: coalesced LDG
    for (int i = tid; i < cO * cC; i += 256) {
        int o = i >> 6, c = i & 63;
        float w = Wv[i];                       // Wv[o][c], i = o*64+c
        ((float2*)wT)[c * cO + o] = make_float2(w, w);
    }
    __syncthreads();

    int wid  = tid >> 5;          // warp -> o-slice [8*wid, 8*wid+8)
    int lane = tid & 31;
    int i0   = lane * 4;

    ull acc[8][2];
    #pragma unroll
    for (int oo = 0; oo < 8; ++oo) { acc[oo][0] = 0ull; acc[oo][1] = 0ull; }

    #pragma unroll 4
    for (int c = 0; c < cC; ++c) {
        float4 xv = *(const float4*)(xs + c * CH + i0);       // 4 wf, cf
        ull xd0 = ((const ull*)&xv)[0], xd1 = ((const ull*)&xv)[1];
        const ull* wc = wT + c * cO + wid * 8;                // 8 consecutive ull
        ull w[8];
        #pragma unroll
        for (int q = 0; q < 4; ++q) {                         // 4 broadcast LDS.128
            ulonglong2 p = *(const ulonglong2*)(wc + 2 * q);
            w[2 * q] = p.x; w[2 * q + 1] = p.y;
        }
        #pragma unroll
        for (int oo = 0; oo < 8; ++oo) {
            asm("fma.rn.f32x2 %0, %1, %2, %0;" : "+l"(acc[oo][0]) : "l"(xd0), "l"(w[oo]));
            asm("fma.rn.f32x2 %0, %1, %2, %0;" : "+l"(acc[oo][1]) : "l"(xd1), "l"(w[oo]));
        }
    }

    // epilogue: bias + fp16 pack + coalesced 8B stores
    #pragma unroll
    for (int oo = 0; oo < 8; ++oo) {
        int o = wid * 8 + oo;
        float b = __ldg(bv + o);
        float2 f0 = u2f(acc[oo][0]), f1 = u2f(acc[oo][1]);
        __half2 h0 = __floats2half2_rn(f0.x + b, f0.y + b);
        __half2 h1 = __floats2half2_rn(f1.x + b, f1.y + b);
        uint2 p; p.x = *(unsigned*)&h0; p.y = *(unsigned*)&h1;
        *(uint2*)(g_vtenh + ((size_t)(n * cO + o) * TV + i0c + i0) / 2) = p;
    }
}

// ---------------------------------------------------------------------------
// K4: out[n,o,t,v] = sum_u att[n,o,v,u] * vten[n,o,t,u]   (keep from R13)
// ---------------------------------------------------------------------------
constexpr int RS = 26;   // padded row stride (floats)

__global__ void __launch_bounds__(320, 3) k_out(float* __restrict__ out) {
    __shared__ __align__(16) float vtr[2 * cT * RS];     // 6656 fl; reused as outsh
    __shared__ __align__(16) float ash[2 * cV * RS];     // 1300 fl

    int n  = blockIdx.y;
    int op = blockIdx.x;
    int tid = threadIdx.x;
    int obase = n * cO + op * 2;

    // ---- stage vt: linear coalesced half2 reads, f32 scatter into padded rows
    const __half2* vsrc = g_vtenh + (size_t)obase * (TV / 2);  // 3200 half2
    #pragma unroll
    for (int k = 0; k < 10; ++k) {                             // 10*320 = 3200
        int g = k * 320 + tid;
        float2 d = __half22float2(vsrc[g]);
        int r0 = 2 * g;
        int oiA = (r0 >= TV);
        int rA  = r0 - oiA * TV;
        int tA  = rA / cV, uA = rA - tA * cV;
        vtr[oiA * (cT * RS) + tA * RS + uA] = d.x;
        int r1 = r0 + 1;
        int oiB = (r1 >= TV);
        int rB  = r1 - oiB * TV;
        int tB  = rB / cV, uB = rB - tB * cV;
        vtr[oiB * (cT * RS) + tB * RS + uB] = d.y;
    }
    // ---- stage att: 1250 contiguous floats
    const float* asrc = g_att + (size_t)obase * 625;
    for (int i = tid; i < 1250; i += 320) {
        float d = asrc[i];
        int oi2 = (i >= 625);
        int r  = i - oi2 * 625;
        int v  = r / cV, u = r - v * cV;
        ash[oi2 * (cV * RS) + v * RS + u] = d;
    }
    // ---- zero pad columns (u = 25)
    if (tid < 256) {
        int oi2 = tid >> 7, t = tid & 127;
        vtr[oi2 * (cT * RS) + t * RS + cV] = 0.f;
    } else if (tid < 306) {
        int j = tid - 256;
        int oi2 = (j >= 25) ? 1 : 0;
        int v = j - 25 * oi2;
        ash[oi2 * (cV * RS) + v * RS + cV] = 0.f;
    }
    __syncthreads();

    int w  = tid >> 5;
    int tg = tid & 31;
    int oi = (w >= 5) ? 1 : 0;
    int vq = w - 5 * oi;

    const ull* ab  = (const ull*)(ash + oi * (cV * RS) + (vq * 5) * RS); // +vi*13
    const ull* vbb = (const ull*)(vtr + oi * (cT * RS)) + tg * (RS / 2); // +ti*32*13

    ull acc[5][4];
    #pragma unroll
    for (int vi = 0; vi < 5; ++vi)
        #pragma unroll
        for (int ti = 0; ti < 4; ++ti) acc[vi][ti] = 0ull;

    #pragma unroll
    for (int up = 0; up < 13; ++up) {
        ull a_u[5], v_u[4];
        #pragma unroll
        for (int vi = 0; vi < 5; ++vi) a_u[vi] = ab[vi * 13 + up];         // broadcast
        #pragma unroll
        for (int ti = 0; ti < 4; ++ti) v_u[ti] = vbb[ti * (32 * 13) + up]; // cf
        #pragma unroll
        for (int vi = 0; vi < 5; ++vi)
            #pragma unroll
            for (int ti = 0; ti < 4; ++ti)
                asm("fma.rn.f32x2 %0, %1, %2, %0;"
                    : "+l"(acc[vi][ti]) : "l"(a_u[vi]), "l"(v_u[ti]));
    }
    __syncthreads();   // all reads of vtr done -> reuse as output buffer

    // ---- results into smem (unpadded t*25+v; lane stride 25 -> conflict-free)
    float* outsh = vtr;
    #pragma unroll
    for (int ti = 0; ti < 4; ++ti) {
        int t = ti * 32 + tg;
        #pragma unroll
        for (int vi = 0; vi < 5; ++vi) {
            float2 f = u2f(acc[vi][ti]);
            outsh[oi * TV + t * cV + vq * 5 + vi] = f.x + f.y;
        }
    }
    __syncthreads();

    // ---- linear coalesced writeback
    float* odst = out + (size_t)obase * TV;
    #pragma unroll
    for (int k = 0; k < 20; ++k) {
        int i = k * 320 + tid;
        odst[i] = outsh[i];
    }
}

// ---------------------------------------------------------------------------
extern "C" void kernel_launch(void* const* d_in, const int* in_sizes, int n_in,
                              void* d_out, int out_size) {
    const float* x    = (const float*)d_in[0];
    const float* adj  = (const float*)d_in[1];
    const float* Wk   = (const float*)d_in[2];
    const float* bk   = (const float*)d_in[3];
    const float* Wq   = (const float*)d_in[4];
    const float* bq   = (const float*)d_in[5];
    const float* Wv   = (const float*)d_in[6];
    const float* bv   = (const float*)d_in[7];
    const float* c1w  = (const float*)d_in[8];
    const float* c1b  = (const float*)d_in[9];
    const float* c2w  = (const float*)d_in[10];
    const float* c2b  = (const float*)d_in[11];
    const float* fw   = (const float*)d_in[12];
    const float* fb   = (const float*)d_in[13];
    const float* alpha= (const float*)d_in[14];
    float* out = (float*)d_out;

    k_sum_t<<<dim3(8, cN), 256>>>(x);
    k_att_kernel<<<dim3(2, cN), 256>>>(adj, Wk, bk, Wq, bq, c1w, c1b, c2w, c2b, fw, fb, alpha);
    k_vten<<<dim3(TV / CH, cN), 256>>>(x, Wv, bv);
    k_out<<<dim3(cO / 2, cN), 320>>>(out);
}

// round 16
// speedup vs baseline: 1.0011x; 1.0011x over previous
#include <cuda_runtime.h>
#include <cuda_fp16.h>

typedef unsigned long long ull;

constexpr int cN = 256, cC = 64, cT = 128, cV = 25, cO = 64;
constexpr int TV  = cT * cV;          // 3200 contiguous (t,v) per (n, channel)

// scratch (no allocations allowed)
__device__ float   g_xsum[cN * cC * cV];                    // 1.6 MB
__device__ float   g_att[(size_t)cN * cO * cV * cV];        // 41 MB
__device__ __half2 g_vtenh[(size_t)cN * cO * TV / 2];       // 105 MB

__device__ __forceinline__ float2 u2f(ull v) {
    float2 r;
    asm("mov.b64 {%0, %1}, %2;" : "=f"(r.x), "=f"(r.y) : "l"(v));
    return r;
}

// ---------------------------------------------------------------------------
// K1: xsum[n,c,v] = sum_t x[n,c,t,v]   (HBM-roof bound, ~40us, keep)
// ---------------------------------------------------------------------------
__global__ void k_sum_t(const float* __restrict__ x) {
    int n = blockIdx.y;
    int c = blockIdx.x * 8 + (threadIdx.x >> 5);
    int lane = threadIdx.x & 31;
    if (lane < cV) {
        const float* p = x + ((size_t)(n * cC + c) * cT) * cV + lane;
        float s = 0.f;
        #pragma unroll 8
        for (int t = 0; t < cT; ++t) s += p[t * cV];
        g_xsum[(n * cC + c) * cV + lane] = s;
    }
}

// ---------------------------------------------------------------------------
// K2: attention matrix (keep)
// ---------------------------------------------------------------------------
__global__ void __launch_bounds__(256) k_att_kernel(
    const float* __restrict__ adj,
    const float* __restrict__ Wk, const float* __restrict__ bk,
    const float* __restrict__ Wq, const float* __restrict__ bq,
    const float* __restrict__ c1w, const float* __restrict__ c1b,
    const float* __restrict__ c2w, const float* __restrict__ c2b,
    const float* __restrict__ fw,  const float* __restrict__ fb,
    const float* __restrict__ alpha) {
    __shared__ float xs2[cC * cV];
    __shared__ float ksh[4 * cV], qsh[4 * cV];
    __shared__ float fwal[cO * 8];              // alpha * fw
    __shared__ float adjsh[cV * cV];
    __shared__ float aa[625 * 9];               // tanh features, stride 9
    __shared__ float c1sh[16], c2sh[16], c1bs[4], c2bs[4], fbal[cO], bks[4], bqs[4];

    int n = blockIdx.y, oh = blockIdx.x, tid = threadIdx.x;
    float al = alpha[0];
    for (int i = tid; i < cC * cV; i += 256) xs2[i] = g_xsum[n * cC * cV + i];
    for (int i = tid; i < cO * 8; i += 256)  fwal[i] = al * fw[i];
    for (int i = tid; i < cV * cV; i += 256) adjsh[i] = adj[i];
    if (tid < 16) { c1sh[tid] = c1w[tid]; c2sh[tid] = c2w[tid]; }
    if (tid < 4)  { c1bs[tid] = c1b[tid]; c2bs[tid] = c2b[tid]; bks[tid] = bk[tid]; bqs[tid] = bq[tid]; }
    if (tid < cO) fbal[tid] = al * fb[tid];
    __syncthreads();

    if (tid < 100) {
        int r = tid / cV, v = tid % cV;
        float a = 0.f;
        for (int c = 0; c < cC; ++c) a += Wk[r * cC + c] * xs2[c * cV + v];
        ksh[tid] = a * (1.f / cT) + bks[r];
    } else if (tid < 200) {
        int j = tid - 100;
        int r = j / cV, v = j % cV;
        float a = 0.f;
        for (int c = 0; c < cC; ++c) a += Wq[r * cC + c] * xs2[c * cV + v];
        qsh[j] = a * (1.f / cT) + bqs[r];
    }
    __syncthreads();

    for (int p = tid; p < 625; p += 256) {
        int v = p / cV, u = p - v * cV;
        float kv[4], qu[4];
        #pragma unroll
        for (int r = 0; r < 4; ++r) { kv[r] = ksh[r * cV + v]; qu[r] = qsh[r * cV + u]; }
        #pragma unroll
        for (int s = 0; s < 4; ++s) {
            float s1 = c1bs[s], s2 = c2bs[s];
            #pragma unroll
            for (int r = 0; r < 4; ++r) {
                s1 += c1sh[s * 4 + r] * (kv[r] * qu[r]);
                s2 += c2sh[s * 4 + r] * (kv[r] - qu[r]);
            }
            aa[p * 9 + s]     = tanhf(s1);
            aa[p * 9 + 4 + s] = tanhf(s2);
        }
    }
    __syncthreads();

    int o0 = oh * 32;
    for (int o = o0; o < o0 + 32; ++o) {
        float w0 = fwal[o*8+0], w1 = fwal[o*8+1], w2 = fwal[o*8+2], w3 = fwal[o*8+3];
        float w4 = fwal[o*8+4], w5 = fwal[o*8+5], w6 = fwal[o*8+6], w7 = fwal[o*8+7];
        float fb_ = fbal[o];
        float* dst = g_att + (size_t)(n * cO + o) * 625;
        for (int p = tid; p < 625; p += 256) {
            const float* a = aa + p * 9;
            float acc = fb_ + adjsh[p];
            acc += w0 * a[0]; acc += w1 * a[1]; acc += w2 * a[2]; acc += w3 * a[3];
            acc += w4 * a[4]; acc += w5 * a[5]; acc += w6 * a[6]; acc += w7 * a[7];
            dst[p] = acc;
        }
    }
}

// ---------------------------------------------------------------------------
// K3 v4: vten[n,o,i] = sum_c Wv[o,c]*x[n,c,i] + bv[o]  -> fp16 store
// Same mainloop as v3 (warp-uniform o-slice, 4 broadcast LDS.128 for w,
// 1 cf LDS.128 for x, 16 FFMA2 per c per warp). STAGING FIX: iterate with
// o per-lane (o = i&63) so STS.64 is conflict-free (was a 32-way conflict
// in v3 -> ~8K crossbar cycles/block, the R15 regression). The Wv LDG
// becomes strided but Wv is 16KB and L1-persistent within the launch.
// ---------------------------------------------------------------------------
constexpr int CH = 128;  // i-chunk

__global__ void __launch_bounds__(256, 3) k_vten(
    const float* __restrict__ x, const float* __restrict__ Wv,
    const float* __restrict__ bv) {
    __shared__ __align__(16) float xs[cC * CH];   // 32 KB
    __shared__ __align__(16) ull   wT[cC * cO];   // 32 KB: wT[c*64+o] = dup Wv[o][c]

    int n   = blockIdx.y;
    int i0c = blockIdx.x * CH;
    int tid = threadIdx.x;

    // stage x chunk: 2048 float4, coalesced, conflict-free
    for (int i = tid; i < cC * (CH / 4); i += 256) {
        int c = i >> 5, j = i & 31;
        ((float4*)xs)[i] =
            ((const float4*)(x + (size_t)(n * cC + c) * TV + i0c))[j];
    }
    // stage transposed+duplicated weights.
    // o per-lane -> consecutive lanes write consecutive o: conflict-free STS.64.
    // LDG Wv[o*64+c] is strided (32 sectors/warp) but 16KB, L1-resident.
    for (int i = tid; i < cO * cC; i += 256) {
        int c = i >> 6, o = i & 63;
        float w = Wv[o * cC + c];
        ((float2*)wT)[c * cO + o] = make_float2(w, w);
    }
    __syncthreads();

    int wid  = tid >> 5;          // warp -> o-slice [8*wid, 8*wid+8)
    int lane = tid & 31;
    int i0   = lane * 4;

    ull acc[8][2];
    #pragma unroll
    for (int oo = 0; oo < 8; ++oo) { acc[oo][0] = 0ull; acc[oo][1] = 0ull; }

    #pragma unroll 4
    for (int c = 0; c < cC; ++c) {
        float4 xv = *(const float4*)(xs + c * CH + i0);       // 4 wf, cf
        ull xd0 = ((const ull*)&xv)[0], xd1 = ((const ull*)&xv)[1];
        const ull* wc = wT + c * cO + wid * 8;                // 8 consecutive ull
        ull w[8];
        #pragma unroll
        for (int q = 0; q < 4; ++q) {                         // 4 broadcast LDS.128
            ulonglong2 p = *(const ulonglong2*)(wc + 2 * q);
            w[2 * q] = p.x; w[2 * q + 1] = p.y;
        }
        #pragma unroll
        for (int oo = 0; oo < 8; ++oo) {
            asm("fma.rn.f32x2 %0, %1, %2, %0;" : "+l"(acc[oo][0]) : "l"(xd0), "l"(w[oo]));
            asm("fma.rn.f32x2 %0, %1, %2, %0;" : "+l"(acc[oo][1]) : "l"(xd1), "l"(w[oo]));
        }
    }

    // epilogue: bias + fp16 pack + coalesced 8B stores
    #pragma unroll
    for (int oo = 0; oo < 8; ++oo) {
        int o = wid * 8 + oo;
        float b = __ldg(bv + o);
        float2 f0 = u2f(acc[oo][0]), f1 = u2f(acc[oo][1]);
        __half2 h0 = __floats2half2_rn(f0.x + b, f0.y + b);
        __half2 h1 = __floats2half2_rn(f1.x + b, f1.y + b);
        uint2 p; p.x = *(unsigned*)&h0; p.y = *(unsigned*)&h1;
        *(uint2*)(g_vtenh + ((size_t)(n * cO + o) * TV + i0c + i0) / 2) = p;
    }
}

// ---------------------------------------------------------------------------
// K4: out[n,o,t,v] = sum_u att[n,o,v,u] * vten[n,o,t,u]   (keep from R13)
// ---------------------------------------------------------------------------
constexpr int RS = 26;   // padded row stride (floats)

__global__ void __launch_bounds__(320, 3) k_out(float* __restrict__ out) {
    __shared__ __align__(16) float vtr[2 * cT * RS];     // 6656 fl; reused as outsh
    __shared__ __align__(16) float ash[2 * cV * RS];     // 1300 fl

    int n  = blockIdx.y;
    int op = blockIdx.x;
    int tid = threadIdx.x;
    int obase = n * cO + op * 2;

    // ---- stage vt: linear coalesced half2 reads, f32 scatter into padded rows
    const __half2* vsrc = g_vtenh + (size_t)obase * (TV / 2);  // 3200 half2
    #pragma unroll
    for (int k = 0; k < 10; ++k) {                             // 10*320 = 3200
        int g = k * 320 + tid;
        float2 d = __half22float2(vsrc[g]);
        int r0 = 2 * g;
        int oiA = (r0 >= TV);
        int rA  = r0 - oiA * TV;
        int tA  = rA / cV, uA = rA - tA * cV;
        vtr[oiA * (cT * RS) + tA * RS + uA] = d.x;
        int r1 = r0 + 1;
        int oiB = (r1 >= TV);
        int rB  = r1 - oiB * TV;
        int tB  = rB / cV, uB = rB - tB * cV;
        vtr[oiB * (cT * RS) + tB * RS + uB] = d.y;
    }
    // ---- stage att: 1250 contiguous floats
    const float* asrc = g_att + (size_t)obase * 625;
    for (int i = tid; i < 1250; i += 320) {
        float d = asrc[i];
        int oi2 = (i >= 625);
        int r  = i - oi2 * 625;
        int v  = r / cV, u = r - v * cV;
        ash[oi2 * (cV * RS) + v * RS + u] = d;
    }
    // ---- zero pad columns (u = 25)
    if (tid < 256) {
        int oi2 = tid >> 7, t = tid & 127;
        vtr[oi2 * (cT * RS) + t * RS + cV] = 0.f;
    } else if (tid < 306) {
        int j = tid - 256;
        int oi2 = (j >= 25) ? 1 : 0;
        int v = j - 25 * oi2;
        ash[oi2 * (cV * RS) + v * RS + cV] = 0.f;
    }
    __syncthreads();

    int w  = tid >> 5;
    int tg = tid & 31;
    int oi = (w >= 5) ? 1 : 0;
    int vq = w - 5 * oi;

    const ull* ab  = (const ull*)(ash + oi * (cV * RS) + (vq * 5) * RS); // +vi*13
    const ull* vbb = (const ull*)(vtr + oi * (cT * RS)) + tg * (RS / 2); // +ti*32*13

    ull acc[5][4];
    #pragma unroll
    for (int vi = 0; vi < 5; ++vi)
        #pragma unroll
        for (int ti = 0; ti < 4; ++ti) acc[vi][ti] = 0ull;

    #pragma unroll
    for (int up = 0; up < 13; ++up) {
        ull a_u[5], v_u[4];
        #pragma unroll
        for (int vi = 0; vi < 5; ++vi) a_u[vi] = ab[vi * 13 + up];         // broadcast
        #pragma unroll
        for (int ti = 0; ti < 4; ++ti) v_u[ti] = vbb[ti * (32 * 13) + up]; // cf
        #pragma unroll
        for (int vi = 0; vi < 5; ++vi)
            #pragma unroll
            for (int ti = 0; ti < 4; ++ti)
                asm("fma.rn.f32x2 %0, %1, %2, %0;"
                    : "+l"(acc[vi][ti]) : "l"(a_u[vi]), "l"(v_u[ti]));
    }
    __syncthreads();   // all reads of vtr done -> reuse as output buffer

    // ---- results into smem (unpadded t*25+v; lane stride 25 -> conflict-free)
    float* outsh = vtr;
    #pragma unroll
    for (int ti = 0; ti < 4; ++ti) {
        int t = ti * 32 + tg;
        #pragma unroll
        for (int vi = 0; vi < 5; ++vi) {
            float2 f = u2f(acc[vi][ti]);
            outsh[oi * TV + t * cV + vq * 5 + vi] = f.x + f.y;
        }
    }
    __syncthreads();

    // ---- linear coalesced writeback
    float* odst = out + (size_t)obase * TV;
    #pragma unroll
    for (int k = 0; k < 20; ++k) {
        int i = k * 320 + tid;
        odst[i] = outsh[i];
    }
}

// ---------------------------------------------------------------------------
extern "C" void kernel_launch(void* const* d_in, const int* in_sizes, int n_in,
                              void* d_out, int out_size) {
    const float* x    = (const float*)d_in[0];
    const float* adj  = (const float*)d_in[1];
    const float* Wk   = (const float*)d_in[2];
    const float* bk   = (const float*)d_in[3];
    const float* Wq   = (const float*)d_in[4];
    const float* bq   = (const float*)d_in[5];
    const float* Wv   = (const float*)d_in[6];
    const float* bv   = (const float*)d_in[7];
    const float* c1w  = (const float*)d_in[8];
    const float* c1b  = (const float*)d_in[9];
    const float* c2w  = (const float*)d_in[10];
    const float* c2b  = (const float*)d_in[11];
    const float* fw   = (const float*)d_in[12];
    const float* fb   = (const float*)d_in[13];
    const float* alpha= (const float*)d_in[14];
    float* out = (float*)d_out;

    k_sum_t<<<dim3(8, cN), 256>>>(x);
    k_att_kernel<<<dim3(2, cN), 256>>>(adj, Wk, bk, Wq, bq, c1w, c1b, c2w, c2b, fw, fb, alpha);
    k_vten<<<dim3(TV / CH, cN), 256>>>(x, Wv, bv);
    k_out<<<dim3(cO / 2, cN), 320>>>(out);
}

// round 17
// speedup vs baseline: 1.2527x; 1.2514x over previous
#include <cuda_runtime.h>
#include <cuda_fp16.h>

typedef unsigned long long ull;

constexpr int cN = 256, cC = 64, cT = 128, cV = 25, cO = 64;
constexpr int TV  = cT * cV;          // 3200 contiguous (t,v) per (n, channel)

// scratch (no allocations allowed)
__device__ float   g_xsum[cN * cC * cV];                    // 1.6 MB
__device__ float   g_att[(size_t)cN * cO * cV * cV];        // 41 MB
__device__ __half2 g_vtenh[(size_t)cN * cO * TV / 2];       // 105 MB

__device__ __forceinline__ float2 u2f(ull v) {
    float2 r;
    asm("mov.b64 {%0, %1}, %2;" : "=f"(r.x), "=f"(r.y) : "l"(v));
    return r;
}
__device__ __forceinline__ unsigned f2tf32(float f) {
    unsigned r;
    asm("cvt.rna.tf32.f32 %0, %1;" : "=r"(r) : "f"(f));
    return r;
}

// ---------------------------------------------------------------------------
// K1: xsum[n,c,v] = sum_t x[n,c,t,v]   (HBM-roof bound, ~40us, keep)
// ---------------------------------------------------------------------------
__global__ void k_sum_t(const float* __restrict__ x) {
    int n = blockIdx.y;
    int c = blockIdx.x * 8 + (threadIdx.x >> 5);
    int lane = threadIdx.x & 31;
    if (lane < cV) {
        const float* p = x + ((size_t)(n * cC + c) * cT) * cV + lane;
        float s = 0.f;
        #pragma unroll 8
        for (int t = 0; t < cT; ++t) s += p[t * cV];
        g_xsum[(n * cC + c) * cV + lane] = s;
    }
}

// ---------------------------------------------------------------------------
// K2: attention matrix (keep)
// ---------------------------------------------------------------------------
__global__ void __launch_bounds__(256) k_att_kernel(
    const float* __restrict__ adj,
    const float* __restrict__ Wk, const float* __restrict__ bk,
    const float* __restrict__ Wq, const float* __restrict__ bq,
    const float* __restrict__ c1w, const float* __restrict__ c1b,
    const float* __restrict__ c2w, const float* __restrict__ c2b,
    const float* __restrict__ fw,  const float* __restrict__ fb,
    const float* __restrict__ alpha) {
    __shared__ float xs2[cC * cV];
    __shared__ float ksh[4 * cV], qsh[4 * cV];
    __shared__ float fwal[cO * 8];              // alpha * fw
    __shared__ float adjsh[cV * cV];
    __shared__ float aa[625 * 9];               // tanh features, stride 9
    __shared__ float c1sh[16], c2sh[16], c1bs[4], c2bs[4], fbal[cO], bks[4], bqs[4];

    int n = blockIdx.y, oh = blockIdx.x, tid = threadIdx.x;
    float al = alpha[0];
    for (int i = tid; i < cC * cV; i += 256) xs2[i] = g_xsum[n * cC * cV + i];
    for (int i = tid; i < cO * 8; i += 256)  fwal[i] = al * fw[i];
    for (int i = tid; i < cV * cV; i += 256) adjsh[i] = adj[i];
    if (tid < 16) { c1sh[tid] = c1w[tid]; c2sh[tid] = c2w[tid]; }
    if (tid < 4)  { c1bs[tid] = c1b[tid]; c2bs[tid] = c2b[tid]; bks[tid] = bk[tid]; bqs[tid] = bq[tid]; }
    if (tid < cO) fbal[tid] = al * fb[tid];
    __syncthreads();

    if (tid < 100) {
        int r = tid / cV, v = tid % cV;
        float a = 0.f;
        for (int c = 0; c < cC; ++c) a += Wk[r * cC + c] * xs2[c * cV + v];
        ksh[tid] = a * (1.f / cT) + bks[r];
    } else if (tid < 200) {
        int j = tid - 100;
        int r = j / cV, v = j % cV;
        float a = 0.f;
        for (int c = 0; c < cC; ++c) a += Wq[r * cC + c] * xs2[c * cV + v];
        qsh[j] = a * (1.f / cT) + bqs[r];
    }
    __syncthreads();

    for (int p = tid; p < 625; p += 256) {
        int v = p / cV, u = p - v * cV;
        float kv[4], qu[4];
        #pragma unroll
        for (int r = 0; r < 4; ++r) { kv[r] = ksh[r * cV + v]; qu[r] = qsh[r * cV + u]; }
        #pragma unroll
        for (int s = 0; s < 4; ++s) {
            float s1 = c1bs[s], s2 = c2bs[s];
            #pragma unroll
            for (int r = 0; r < 4; ++r) {
                s1 += c1sh[s * 4 + r] * (kv[r] * qu[r]);
                s2 += c2sh[s * 4 + r] * (kv[r] - qu[r]);
            }
            aa[p * 9 + s]     = tanhf(s1);
            aa[p * 9 + 4 + s] = tanhf(s2);
        }
    }
    __syncthreads();

    int o0 = oh * 32;
    for (int o = o0; o < o0 + 32; ++o) {
        float w0 = fwal[o*8+0], w1 = fwal[o*8+1], w2 = fwal[o*8+2], w3 = fwal[o*8+3];
        float w4 = fwal[o*8+4], w5 = fwal[o*8+5], w6 = fwal[o*8+6], w7 = fwal[o*8+7];
        float fb_ = fbal[o];
        float* dst = g_att + (size_t)(n * cO + o) * 625;
        for (int p = tid; p < 625; p += 256) {
            const float* a = aa + p * 9;
            float acc = fb_ + adjsh[p];
            acc += w0 * a[0]; acc += w1 * a[1]; acc += w2 * a[2]; acc += w3 * a[3];
            acc += w4 * a[4]; acc += w5 * a[5]; acc += w6 * a[6]; acc += w7 * a[7];
            dst[p] = acc;
        }
    }
}

// ---------------------------------------------------------------------------
// K3 v5: TENSOR-CORE vten. C[64o x 128i] = W[64x64] @ x[64c x 128i] + bv.
// tf32 mma.sync.m16n8k8, fp32 accum, fp16 output.
// 256 thr = 8 warps: warp -> (o-tile mt = wid&3 [16 o], i-half nh = wid>>2
// [64 i]). A-frags (W) loaded ONCE into 32 regs; B-frags from xs.
// Padded strides: xs 136 (8 mod 32 -> b-frag LDS.32 conflict-free),
// ws 68 (4 mod 32 -> a-frag conflict-free). tf32 conversion at staging
// (cvt.rna). Epilogue: c-frags -> padded smem (stride 68 half2,
// conflict-free) -> linear coalesced half2 writeback.
// ---------------------------------------------------------------------------
constexpr int CH   = 128;            // i-chunk
constexpr int XSS  = 136;            // xs row stride (floats)
constexpr int WSS  = 68;             // ws row stride (floats)
constexpr int HBS  = 68;             // epilogue half2 row stride
constexpr int VSM  = (cC * XSS + cO * WSS) * 4;   // 52224 B dyn smem

__global__ void __launch_bounds__(256, 2) k_vten(
    const float* __restrict__ x, const float* __restrict__ Wv,
    const float* __restrict__ bv) {
    extern __shared__ float sm[];
    float* xs = sm;                    // [64][136] tf32
    float* ws = sm + cC * XSS;         // [64][68]  tf32

    int n   = blockIdx.y;
    int i0c = blockIdx.x * CH;
    int tid = threadIdx.x;

    // stage x (tf32-converted), vectorized stores, conflict-free
    for (int idx = tid; idx < cC * (CH / 4); idx += 256) {
        int c = idx >> 5, j = idx & 31;
        float4 v = ((const float4*)(x + (size_t)(n * cC + c) * TV + i0c))[j];
        float4 t;
        t.x = __uint_as_float(f2tf32(v.x));
        t.y = __uint_as_float(f2tf32(v.y));
        t.z = __uint_as_float(f2tf32(v.z));
        t.w = __uint_as_float(f2tf32(v.w));
        *(float4*)(xs + c * XSS + 4 * j) = t;
    }
    // stage W (tf32-converted)
    for (int idx = tid; idx < cO * (cC / 4); idx += 256) {
        int o = idx >> 4, j = idx & 15;
        float4 v = ((const float4*)(Wv + o * cC))[j];
        float4 t;
        t.x = __uint_as_float(f2tf32(v.x));
        t.y = __uint_as_float(f2tf32(v.y));
        t.z = __uint_as_float(f2tf32(v.z));
        t.w = __uint_as_float(f2tf32(v.w));
        *(float4*)(ws + o * WSS + 4 * j) = t;
    }
    __syncthreads();

    int wid = tid >> 5, lane = tid & 31;
    int mt = wid & 3, nh = wid >> 2;
    int o0 = mt * 16;
    int r  = lane >> 2, cb = lane & 3;

    // A-frags: a[ks][0..3] for k0 = 8*ks  (all conflict-free LDS.32)
    unsigned a[8][4];
    #pragma unroll
    for (int ks = 0; ks < 8; ++ks) {
        const float* w0 = ws + (o0 + r) * WSS + ks * 8 + cb;
        a[ks][0] = __float_as_uint(w0[0]);
        a[ks][1] = __float_as_uint(w0[8 * WSS]);
        a[ks][2] = __float_as_uint(w0[4]);
        a[ks][3] = __float_as_uint(w0[8 * WSS + 4]);
    }

    // mainloop: 8 n-tiles x 8 k-steps
    float d[8][4];
    #pragma unroll
    for (int nt = 0; nt < 8; ++nt)
        #pragma unroll
        for (int q = 0; q < 4; ++q) d[nt][q] = 0.f;

    #pragma unroll
    for (int nt = 0; nt < 8; ++nt) {
        int ib = nh * 64 + nt * 8 + (lane >> 2);
        #pragma unroll
        for (int ks = 0; ks < 8; ++ks) {
            unsigned b0 = __float_as_uint(xs[(ks * 8 + cb) * XSS + ib]);
            unsigned b1 = __float_as_uint(xs[(ks * 8 + cb + 4) * XSS + ib]);
            asm("mma.sync.aligned.m16n8k8.row.col.f32.tf32.tf32.f32 "
                "{%0,%1,%2,%3}, {%4,%5,%6,%7}, {%8,%9}, {%0,%1,%2,%3};"
                : "+f"(d[nt][0]), "+f"(d[nt][1]), "+f"(d[nt][2]), "+f"(d[nt][3])
                : "r"(a[ks][0]), "r"(a[ks][1]), "r"(a[ks][2]), "r"(a[ks][3]),
                  "r"(b0), "r"(b1));
        }
    }
    __syncthreads();   // all xs/ws reads done -> reuse xs region as hb

    // epilogue: c-frags + bias -> half2 in padded smem (conflict-free STS.32)
    __half2* hb = (__half2*)xs;        // [64 o][HBS=68] half2 (i-pairs)
    float blo = __ldg(bv + o0 + r);
    float bhi = __ldg(bv + o0 + r + 8);
    #pragma unroll
    for (int nt = 0; nt < 8; ++nt) {
        int ip = nh * 32 + nt * 4 + cb;
        hb[(o0 + r)     * HBS + ip] = __floats2half2_rn(d[nt][0] + blo, d[nt][1] + blo);
        hb[(o0 + r + 8) * HBS + ip] = __floats2half2_rn(d[nt][2] + bhi, d[nt][3] + bhi);
    }
    __syncthreads();

    // linear coalesced writeback: 4096 half2
    __half2* dst = g_vtenh + ((size_t)(n * cO) * TV + i0c) / 2;
    #pragma unroll
    for (int k = 0; k < 16; ++k) {
        int idx = k * 256 + tid;
        int o = idx >> 6, ip = idx & 63;
        dst[(size_t)o * (TV / 2) + ip] = hb[o * HBS + ip];
    }
}

// ---------------------------------------------------------------------------
// K4: out[n,o,t,v] = sum_u att[n,o,v,u] * vten[n,o,t,u]   (keep from R13)
// ---------------------------------------------------------------------------
constexpr int RS = 26;   // padded row stride (floats)

__global__ void __launch_bounds__(320, 3) k_out(float* __restrict__ out) {
    __shared__ __align__(16) float vtr[2 * cT * RS];     // 6656 fl; reused as outsh
    __shared__ __align__(16) float ash[2 * cV * RS];     // 1300 fl

    int n  = blockIdx.y;
    int op = blockIdx.x;
    int tid = threadIdx.x;
    int obase = n * cO + op * 2;

    // ---- stage vt: linear coalesced half2 reads, f32 scatter into padded rows
    const __half2* vsrc = g_vtenh + (size_t)obase * (TV / 2);  // 3200 half2
    #pragma unroll
    for (int k = 0; k < 10; ++k) {                             // 10*320 = 3200
        int g = k * 320 + tid;
        float2 d = __half22float2(vsrc[g]);
        int r0 = 2 * g;
        int oiA = (r0 >= TV);
        int rA  = r0 - oiA * TV;
        int tA  = rA / cV, uA = rA - tA * cV;
        vtr[oiA * (cT * RS) + tA * RS + uA] = d.x;
        int r1 = r0 + 1;
        int oiB = (r1 >= TV);
        int rB  = r1 - oiB * TV;
        int tB  = rB / cV, uB = rB - tB * cV;
        vtr[oiB * (cT * RS) + tB * RS + uB] = d.y;
    }
    // ---- stage att: 1250 contiguous floats
    const float* asrc = g_att + (size_t)obase * 625;
    for (int i = tid; i < 1250; i += 320) {
        float d = asrc[i];
        int oi2 = (i >= 625);
        int r  = i - oi2 * 625;
        int v  = r / cV, u = r - v * cV;
        ash[oi2 * (cV * RS) + v * RS + u] = d;
    }
    // ---- zero pad columns (u = 25)
    if (tid < 256) {
        int oi2 = tid >> 7, t = tid & 127;
        vtr[oi2 * (cT * RS) + t * RS + cV] = 0.f;
    } else if (tid < 306) {
        int j = tid - 256;
        int oi2 = (j >= 25) ? 1 : 0;
        int v = j - 25 * oi2;
        ash[oi2 * (cV * RS) + v * RS + cV] = 0.f;
    }
    __syncthreads();

    int w  = tid >> 5;
    int tg = tid & 31;
    int oi = (w >= 5) ? 1 : 0;
    int vq = w - 5 * oi;

    const ull* ab  = (const ull*)(ash + oi * (cV * RS) + (vq * 5) * RS); // +vi*13
    const ull* vbb = (const ull*)(vtr + oi * (cT * RS)) + tg * (RS / 2); // +ti*32*13

    ull acc[5][4];
    #pragma unroll
    for (int vi = 0; vi < 5; ++vi)
        #pragma unroll
        for (int ti = 0; ti < 4; ++ti) acc[vi][ti] = 0ull;

    #pragma unroll
    for (int up = 0; up < 13; ++up) {
        ull a_u[5], v_u[4];
        #pragma unroll
        for (int vi = 0; vi < 5; ++vi) a_u[vi] = ab[vi * 13 + up];         // broadcast
        #pragma unroll
        for (int ti = 0; ti < 4; ++ti) v_u[ti] = vbb[ti * (32 * 13) + up]; // cf
        #pragma unroll
        for (int vi = 0; vi < 5; ++vi)
            #pragma unroll
            for (int ti = 0; ti < 4; ++ti)
                asm("fma.rn.f32x2 %0, %1, %2, %0;"
                    : "+l"(acc[vi][ti]) : "l"(a_u[vi]), "l"(v_u[ti]));
    }
    __syncthreads();   // all reads of vtr done -> reuse as output buffer

    // ---- results into smem (unpadded t*25+v; lane stride 25 -> conflict-free)
    float* outsh = vtr;
    #pragma unroll
    for (int ti = 0; ti < 4; ++ti) {
        int t = ti * 32 + tg;
        #pragma unroll
        for (int vi = 0; vi < 5; ++vi) {
            float2 f = u2f(acc[vi][ti]);
            outsh[oi * TV + t * cV + vq * 5 + vi] = f.x + f.y;
        }
    }
    __syncthreads();

    // ---- linear coalesced writeback
    float* odst = out + (size_t)obase * TV;
    #pragma unroll
    for (int k = 0; k < 20; ++k) {
        int i = k * 320 + tid;
        odst[i] = outsh[i];
    }
}

// ---------------------------------------------------------------------------
extern "C" void kernel_launch(void* const* d_in, const int* in_sizes, int n_in,
                              void* d_out, int out_size) {
    const float* x    = (const float*)d_in[0];
    const float* adj  = (const float*)d_in[1];
    const float* Wk   = (const float*)d_in[2];
    const float* bk   = (const float*)d_in[3];
    const float* Wq   = (const float*)d_in[4];
    const float* bq   = (const float*)d_in[5];
    const float* Wv   = (const float*)d_in[6];
    const float* bv   = (const float*)d_in[7];
    const float* c1w  = (const float*)d_in[8];
    const float* c1b  = (const float*)d_in[9];
    const float* c2w  = (const float*)d_in[10];
    const float* c2b  = (const float*)d_in[11];
    const float* fw   = (const float*)d_in[12];
    const float* fb   = (const float*)d_in[13];
    const float* alpha= (const float*)d_in[14];
    float* out = (float*)d_out;

    cudaFuncSetAttribute((const void*)k_vten,
                         cudaFuncAttributeMaxDynamicSharedMemorySize, VSM);

    k_sum_t<<<dim3(8, cN), 256>>>(x);
    k_att_kernel<<<dim3(2, cN), 256>>>(adj, Wk, bk, Wq, bq, c1w, c1b, c2w, c2b, fw, fb, alpha);
    k_vten<<<dim3(TV / CH, cN), 256, VSM>>>(x, Wv, bv);
    k_out<<<dim3(cO / 2, cN), 320>>>(out);
}